// round 4
// baseline (speedup 1.0000x reference)
#include <cuda_runtime.h>

#define B 128
#define L 200
#define D 50
#define H 5
#define E 10
#define NB 2
#define DH 10

typedef unsigned long long ull;

#define FMA2(d,a,b,c) asm("fma.rn.f32x2 %0, %1, %2, %3;" : "=l"(d) : "l"(a), "l"(b), "l"(c))

__device__ __forceinline__ float hadd2(ull v) {
    float lo, hi; asm("mov.b64 {%0,%1}, %2;" : "=f"(lo), "=f"(hi) : "l"(v)); return lo + hi;
}
__device__ __forceinline__ ull pack2(float a, float b) {
    ull r; asm("mov.b64 %0, {%1,%2};" : "=l"(r) : "f"(a), "f"(b)); return r;
}
__device__ __forceinline__ void unpk2(ull v, float& lo, float& hi) {
    asm("mov.b64 {%0,%1}, %2;" : "=f"(lo), "=f"(hi) : "l"(v));
}

// ---------------- scratch (device globals; allocation-free) ----------------
__device__ __align__(16) float g_seqs[B*L*D];
__device__ __align__(16) float g_tmp [B*L*D];
__device__ __align__(16) float g_Qn  [B*L*D];
__device__ __align__(16) float g_gate[B*E];
__device__ __align__(16) float g_q   [B*E*H*L*DH];   // [be, h, l, dh]
__device__ __align__(16) float g_k   [B*E*H*L*DH];
__device__ __align__(16) float g_v   [B*E*H*L*DH];
__device__ __align__(16) float g_ctx [B*E*L*D];      // [be, l, d]  (gate pre-folded)

// ---------------- gate MLP ----------------
__global__ void k_gate(const float* __restrict__ item_emb,
                       const float* __restrict__ rW1, const float* __restrict__ rb1,
                       const float* __restrict__ rW2, const float* __restrict__ rb2,
                       const int* __restrict__ log_seqs) {
    __shared__ float mean[D];
    __shared__ float h[100];
    __shared__ float logit[E];
    int b = blockIdx.x, t = threadIdx.x;
    if (t < D) {
        float acc = 0.f;
        for (int l = 0; l < L; ++l) {
            int it = log_seqs[b*L + l];
            acc += item_emb[it*D + t];
        }
        mean[t] = acc * (7.0710678118654755f / 200.0f);
    }
    __syncthreads();
    if (t < 100) {
        float acc = rb1[t];
        #pragma unroll
        for (int d = 0; d < D; ++d) acc = fmaf(mean[d], rW1[t*D + d], acc);
        h[t] = fmaxf(acc, 0.f);
    }
    __syncthreads();
    if (t < E) {
        float acc = rb2[t];
        #pragma unroll
        for (int j = 0; j < 100; ++j) acc = fmaf(h[j], rW2[t*100 + j], acc);
        logit[t] = acc;
    }
    __syncthreads();
    if (t == 0) {
        float m = -1e30f;
        #pragma unroll
        for (int e = 0; e < E; ++e) m = fmaxf(m, logit[e]);
        float s = 0.f; float ex[E];
        #pragma unroll
        for (int e = 0; e < E; ++e) { ex[e] = expf(logit[e] - m); s += ex[e]; }
        float inv = 1.0f / s;
        #pragma unroll
        for (int e = 0; e < E; ++e) g_gate[b*E + e] = ex[e] * inv;
    }
}

// ---------------- embedding + positional ----------------
__global__ void k_embed(const float* __restrict__ item_emb,
                        const float* __restrict__ pos_emb,
                        const int* __restrict__ log_seqs) {
    int idx = blockIdx.x*blockDim.x + threadIdx.x;
    if (idx >= B*L*D) return;
    int d = idx % D; int bl = idx / D; int l = bl % L; int b = bl / L;
    int it = log_seqs[b*L + l];
    int pos = (it != 0) ? (l + 1) : 0;
    g_seqs[idx] = item_emb[it*D + d] * 7.0710678118654755f + pos_emb[pos*D + d];
}

// ---------------- layernorm: warp per row ----------------
__global__ void k_ln(int mode, const float* __restrict__ g, const float* __restrict__ bb) {
    int warp = (blockIdx.x*blockDim.x + threadIdx.x) >> 5;
    int lane = threadIdx.x & 31;
    if (warp >= B*L) return;
    const float* in  = (mode == 0) ? g_seqs : g_tmp;
    float*       out = (mode == 0) ? g_Qn   : g_seqs;
    const float* x = in + warp*D;
    float x0 = (lane < D)      ? x[lane]      : 0.f;
    float x1 = (lane + 32 < D) ? x[lane + 32] : 0.f;
    float s = x0 + x1;
    #pragma unroll
    for (int o = 16; o; o >>= 1) s += __shfl_xor_sync(~0u, s, o);
    float m = s * (1.0f / D);
    float d0 = (lane < D)      ? x0 - m : 0.f;
    float d1 = (lane + 32 < D) ? x1 - m : 0.f;
    float v = d0*d0 + d1*d1;
    #pragma unroll
    for (int o = 16; o; o >>= 1) v += __shfl_xor_sync(~0u, v, o);
    float inv = rsqrtf(v * (1.0f / D) + 1e-8f);
    float* y = out + warp*D;
    if (lane < D)      y[lane]      = fmaf(d0*inv, g[lane],      bb[lane]);
    if (lane + 32 < D) y[lane + 32] = fmaf(d1*inv, g[lane + 32], bb[lane + 32]);
}

// ---------------- QKV: CTA per (b,e); thread = row; W broadcast from smem ----------------
// ws layout: float offset i*300 + 2f holds W[f][2i], W[f][2i+1]  (i = k-pair 0..24, f 0..149)
__global__ void __launch_bounds__(224) k_qkv(const float* __restrict__ in_w,
                                             const float* __restrict__ in_b, int blk) {
    int b = blockIdx.x, e = blockIdx.y;
    __shared__ __align__(16) float ws[7500];
    __shared__ __align__(16) float sout[200*12];
    __shared__ float sbias[152];
    int tid = threadIdx.x;
    {
        const ull* Wg = (const ull*)(in_w + (size_t)(blk*E + e)*7500);
        ull* wsu = (ull*)ws;
        for (int j = tid; j < 3750; j += 224) {
            int f = j / 25, i = j - f*25;
            wsu[i*150 + f] = Wg[j];
        }
        for (int j = tid; j < 150; j += 224) sbias[j] = in_b[(blk*E + e)*150 + j];
    }
    __syncthreads();
    int l = tid;
    bool valid = l < 200;
    int lrow = valid ? l : 0;
    ull x[25];
    for (int phase = 0; phase < 2; ++phase) {
        const float* src = phase ? (g_seqs + ((size_t)b*L + lrow)*D)
                                 : (g_Qn   + ((size_t)b*L + lrow)*D);
        const ull* xp = (const ull*)src;
        #pragma unroll
        for (int i = 0; i < 25; ++i) x[i] = xp[i];
        int c0 = phase ? 5 : 0, c1 = phase ? 15 : 5;
        for (int c = c0; c < c1; ++c) {
            #pragma unroll
            for (int fp = 0; fp < 5; ++fp) {
                int f = c*10 + 2*fp;
                ull a0 = 0ull, a1 = 0ull;
                #pragma unroll
                for (int i = 0; i < 25; ++i) {
                    float4 w4 = *(const float4*)(ws + i*300 + 2*f);
                    ull wA = pack2(w4.x, w4.y);
                    ull wB = pack2(w4.z, w4.w);
                    FMA2(a0, wA, x[i], a0);
                    FMA2(a1, wB, x[i], a1);
                }
                if (valid) {
                    float v0 = hadd2(a0) + sbias[f];
                    float v1 = hadd2(a1) + sbias[f+1];
                    *(ull*)(sout + l*12 + 2*fp) = pack2(v0, v1);
                }
            }
            __syncthreads();
            int g = c / 5, h = c - g*5;
            float* dst = ((g == 0) ? g_q : (g == 1) ? g_k : g_v)
                         + ((size_t)(b*E + e)*H + h)*L*DH;
            for (int o = tid; o < 2000; o += 224) {
                int lr = o / 10, dd = o - lr*10;
                dst[o] = sout[lr*12 + dd];
            }
            __syncthreads();
        }
    }
}

// ---------------- attention: lane = query row, shuffle-free, gate folded in ----------------
__global__ void __launch_bounds__(224) k_attn() {
    int id = blockIdx.x;            // (b*E+e)*H + h
    int h = id % H; int be = id / H;
    __shared__ __align__(16) float ks[L*DH];
    __shared__ __align__(16) float vs[L*DH];
    {
        const float4* kb = (const float4*)(g_k + (size_t)(be*H + h)*L*DH);
        const float4* vb = (const float4*)(g_v + (size_t)(be*H + h)*L*DH);
        float4* k4 = (float4*)ks; float4* v4 = (float4*)vs;
        for (int i = threadIdx.x; i < 500; i += 224) { k4[i] = kb[i]; v4[i] = vb[i]; }
    }
    __syncthreads();
    int w = threadIdx.x >> 5, lane = threadIdx.x & 31;
    int i = w*32 + lane;
    bool valid = i < L;
    int irow = valid ? i : 0;
    const float scale = 0.31622776601683794f;   // 1/sqrt(10)
    ull q2[5];
    {
        const ull* qp = (const ull*)(g_q + ((size_t)(be*H + h)*L + irow)*DH);
        #pragma unroll
        for (int d = 0; d < 5; ++d) q2[d] = qp[d];
    }
    int jmax = w*32 + 32; if (jmax > L) jmax = L;
    float psum = 0.f;
    ull acc[5] = {0ull,0ull,0ull,0ull,0ull};
    #pragma unroll 2
    for (int j = 0; j < jmax; ++j) {
        const ull* kj = (const ull*)ks + j*5;
        const ull* vj = (const ull*)vs + j*5;
        ull a = 0ull;
        #pragma unroll
        for (int d = 0; d < 5; ++d) FMA2(a, q2[d], kj[d], a);
        float s = hadd2(a) * scale;
        float p = (j <= i) ? __expf(s) : 0.f;
        psum += p;
        ull pp = pack2(p, p);
        #pragma unroll
        for (int d = 0; d < 5; ++d) FMA2(acc[d], pp, vj[d], acc[d]);
    }
    if (valid) {
        int b = be / E, e = be - b*E;
        float gt = g_gate[b*E + e];
        float inv = gt / psum;
        ull* cp = (ull*)(g_ctx + ((size_t)be*L + i)*D + h*DH);
        #pragma unroll
        for (int d = 0; d < 5; ++d) {
            float lo, hi; unpk2(acc[d], lo, hi);
            cp[d] = pack2(lo*inv, hi*inv);
        }
    }
}

// ---------------- out-proj over (e,d) + bias-mix + residual (gate already in ctx) ----------------
__global__ void __launch_bounds__(400) k_combine(const float* __restrict__ out_w,
                                                 const float* __restrict__ out_b, int blk) {
    int b = blockIdx.x;
    int l0 = blockIdx.y * 32;
    __shared__ __align__(16) float wt[2500];   // [i][2f] pairs: float off i*100+2f = W[f][2i..2i+1]
    __shared__ __align__(16) float ct[1600];   // 32 rows x 50
    int tid = threadIdx.x;
    int fc2 = tid % 25, li2 = tid / 25;        // feature pair 2*fc2, rows l0+2*li2(+1)
    ull a00 = 0ull, a01 = 0ull, a10 = 0ull, a11 = 0ull;
    float bm0 = 0.f, bm1 = 0.f;
    for (int e = 0; e < E; ++e) {
        __syncthreads();
        {
            const ull* Wg = (const ull*)(out_w + (size_t)(blk*E + e)*2500);
            ull* wtu = (ull*)wt;
            for (int j = tid; j < 1250; j += 400) {
                int f = j / 25, i = j - f*25;
                wtu[i*50 + f] = Wg[j];
            }
            for (int j = tid; j < 1600; j += 400) {
                int r = j / 50, cc = j - r*50;
                int gr = l0 + r;
                ct[j] = (gr < L) ? g_ctx[((size_t)(b*E + e)*L + gr)*D + cc] : 0.f;
            }
        }
        float ge = g_gate[b*E + e];
        bm0 = fmaf(ge, out_b[(blk*E + e)*D + 2*fc2],     bm0);
        bm1 = fmaf(ge, out_b[(blk*E + e)*D + 2*fc2 + 1], bm1);
        __syncthreads();
        const ull* c0p = (const ull*)(ct + (2*li2)*50);
        const ull* c1p = (const ull*)(ct + (2*li2 + 1)*50);
        #pragma unroll
        for (int i = 0; i < 25; ++i) {
            float4 w4 = *(const float4*)(wt + i*100 + 4*fc2);
            ull wA = pack2(w4.x, w4.y);
            ull wB = pack2(w4.z, w4.w);
            ull cc0 = c0p[i], cc1 = c1p[i];
            FMA2(a00, wA, cc0, a00);
            FMA2(a01, wA, cc1, a01);
            FMA2(a10, wB, cc0, a10);
            FMA2(a11, wB, cc1, a11);
        }
    }
    int r0 = l0 + 2*li2, r1 = r0 + 1;
    if (r0 < L) {
        float q0a, q0b; unpk2(*(const ull*)(g_Qn + ((size_t)b*L + r0)*D + 2*fc2), q0a, q0b);
        *(ull*)(g_tmp + ((size_t)b*L + r0)*D + 2*fc2) =
            pack2(hadd2(a00) + bm0 + q0a, hadd2(a10) + bm1 + q0b);
    }
    if (r1 < L) {
        float q1a, q1b; unpk2(*(const ull*)(g_Qn + ((size_t)b*L + r1)*D + 2*fc2), q1a, q1b);
        *(ull*)(g_tmp + ((size_t)b*L + r1)*D + 2*fc2) =
            pack2(hadd2(a01) + bm0 + q1a, hadd2(a11) + bm1 + q1b);
    }
}

// ---------------- fused FFN (in place on g_seqs) ----------------
__global__ void __launch_bounds__(250) k_ffn(const float* __restrict__ f1_w, const float* __restrict__ f1_b,
                                             const float* __restrict__ f2_w, const float* __restrict__ f2_b,
                                             int blk) {
    int b = blockIdx.x;
    int base = blockIdx.y * 100;
    __shared__ __align__(16) float w1t[2500], w2t[2500];
    __shared__ __align__(16) float xs[500];
    __shared__ __align__(16) float hs[520];    // 10 rows x 52
    __shared__ float b1s[50], b2s[50];
    int tid = threadIdx.x;
    int fc2 = tid % 25, r = tid / 25;          // feature pair, row within chunk
    {
        const ull* W1g = (const ull*)(f1_w + (size_t)blk*2500);
        const ull* W2g = (const ull*)(f2_w + (size_t)blk*2500);
        ull* w1u = (ull*)w1t; ull* w2u = (ull*)w2t;
        for (int j = tid; j < 1250; j += 250) {
            int f = j / 25, i = j - f*25;
            w1u[i*50 + f] = W1g[j];
            w2u[i*50 + f] = W2g[j];
        }
        if (tid < 50) { b1s[tid] = f1_b[blk*D + tid]; b2s[tid] = f2_b[blk*D + tid]; }
    }
    __syncthreads();
    for (int chunk = 0; chunk < 10; ++chunk) {
        int l0 = base + chunk*10;
        for (int j = tid; j < 500; j += 250) xs[j] = g_seqs[((size_t)b*L + l0)*D + j];
        __syncthreads();
        const ull* xp = (const ull*)(xs + r*50);
        ull a0 = 0ull, a1 = 0ull;
        #pragma unroll
        for (int i = 0; i < 25; ++i) {
            float4 w4 = *(const float4*)(w1t + i*100 + 4*fc2);
            FMA2(a0, pack2(w4.x, w4.y), xp[i], a0);
            FMA2(a1, pack2(w4.z, w4.w), xp[i], a1);
        }
        float h0 = fmaxf(hadd2(a0) + b1s[2*fc2],     0.f);
        float h1 = fmaxf(hadd2(a1) + b1s[2*fc2 + 1], 0.f);
        *(ull*)(hs + r*52 + 2*fc2) = pack2(h0, h1);
        __syncthreads();
        const ull* hp = (const ull*)(hs + r*52);
        a0 = 0ull; a1 = 0ull;
        #pragma unroll
        for (int i = 0; i < 25; ++i) {
            float4 w4 = *(const float4*)(w2t + i*100 + 4*fc2);
            FMA2(a0, pack2(w4.x, w4.y), hp[i], a0);
            FMA2(a1, pack2(w4.z, w4.w), hp[i], a1);
        }
        float o0 = hadd2(a0) + b2s[2*fc2]     + xs[r*50 + 2*fc2];
        float o1 = hadd2(a1) + b2s[2*fc2 + 1] + xs[r*50 + 2*fc2 + 1];
        *(ull*)(g_seqs + ((size_t)b*L + l0 + r)*D + 2*fc2) = pack2(o0, o1);
        __syncthreads();
    }
}

// ---------------- final LN + pos/neg logits ----------------
__global__ void k_final(const float* __restrict__ lnf_g, const float* __restrict__ lnf_b,
                        const float* __restrict__ item_emb,
                        const int* __restrict__ pos_seqs, const int* __restrict__ neg_seqs,
                        float* __restrict__ out) {
    int warp = (blockIdx.x*blockDim.x + threadIdx.x) >> 5;
    int lane = threadIdx.x & 31;
    if (warp >= B*L) return;
    const float* x = g_seqs + warp*D;
    float x0 = (lane < D)      ? x[lane]      : 0.f;
    float x1 = (lane + 32 < D) ? x[lane + 32] : 0.f;
    float s = x0 + x1;
    #pragma unroll
    for (int o = 16; o; o >>= 1) s += __shfl_xor_sync(~0u, s, o);
    float m = s * (1.0f / D);
    float d0 = (lane < D)      ? x0 - m : 0.f;
    float d1 = (lane + 32 < D) ? x1 - m : 0.f;
    float v = d0*d0 + d1*d1;
    #pragma unroll
    for (int o = 16; o; o >>= 1) v += __shfl_xor_sync(~0u, v, o);
    float inv = rsqrtf(v * (1.0f / D) + 1e-8f);
    float f0 = (lane < D)      ? fmaf(d0*inv, lnf_g[lane],      lnf_b[lane])      : 0.f;
    float f1 = (lane + 32 < D) ? fmaf(d1*inv, lnf_g[lane + 32], lnf_b[lane + 32]) : 0.f;
    int ip = pos_seqs[warp], in_ = neg_seqs[warp];
    const float* pe = item_emb + (size_t)ip*D;
    const float* ne = item_emb + (size_t)in_*D;
    float dp = 0.f, dn = 0.f;
    if (lane < D)      { dp = f0*pe[lane];                 dn = f0*ne[lane]; }
    if (lane + 32 < D) { dp = fmaf(f1, pe[lane + 32], dp); dn = fmaf(f1, ne[lane + 32], dn); }
    #pragma unroll
    for (int o = 16; o; o >>= 1) {
        dp += __shfl_xor_sync(~0u, dp, o);
        dn += __shfl_xor_sync(~0u, dn, o);
    }
    if (lane == 0) { out[warp] = dp; out[B*L + warp] = dn; }
}

// ---------------- launch ----------------
extern "C" void kernel_launch(void* const* d_in, const int* in_sizes, int n_in,
                              void* d_out, int out_size) {
    const float* item_emb = (const float*)d_in[0];
    const float* pos_emb  = (const float*)d_in[1];
    const float* rW1      = (const float*)d_in[2];
    const float* rb1      = (const float*)d_in[3];
    const float* rW2      = (const float*)d_in[4];
    const float* rb2      = (const float*)d_in[5];
    const float* ln1_g    = (const float*)d_in[6];
    const float* ln1_b    = (const float*)d_in[7];
    const float* in_w     = (const float*)d_in[8];
    const float* in_b     = (const float*)d_in[9];
    const float* out_w    = (const float*)d_in[10];
    const float* out_b    = (const float*)d_in[11];
    const float* ln2_g    = (const float*)d_in[12];
    const float* ln2_b    = (const float*)d_in[13];
    const float* f1_w     = (const float*)d_in[14];
    const float* f1_b     = (const float*)d_in[15];
    const float* f2_w     = (const float*)d_in[16];
    const float* f2_b     = (const float*)d_in[17];
    const float* lnf_g    = (const float*)d_in[18];
    const float* lnf_b    = (const float*)d_in[19];
    const int*   log_seqs = (const int*)d_in[21];
    const int*   pos_seqs = (const int*)d_in[22];
    const int*   neg_seqs = (const int*)d_in[23];
    float* out = (float*)d_out;

    k_gate<<<B, 128>>>(item_emb, rW1, rb1, rW2, rb2, log_seqs);
    k_embed<<<(B*L*D + 255)/256, 256>>>(item_emb, pos_emb, log_seqs);

    for (int blk = 0; blk < NB; ++blk) {
        k_ln<<<(B*L + 7)/8, 256>>>(0, ln1_g + blk*D, ln1_b + blk*D);
        k_qkv<<<dim3(B, E), 224>>>(in_w, in_b, blk);
        k_attn<<<B*E*H, 224>>>();
        k_combine<<<dim3(B, 7), 400>>>(out_w, out_b, blk);
        k_ln<<<(B*L + 7)/8, 256>>>(1, ln2_g + blk*D, ln2_b + blk*D);
        k_ffn<<<dim3(B, 2), 250>>>(f1_w, f1_b, f2_w, f2_b, blk);
    }

    k_final<<<(B*L + 7)/8, 256>>>(lnf_g, lnf_b, item_emb, pos_seqs, neg_seqs, out);
}

// round 5
// speedup vs baseline: 1.0609x; 1.0609x over previous
#include <cuda_runtime.h>

#define B 128
#define L 200
#define D 50
#define H 5
#define E 10
#define NB 2
#define DH 10

typedef unsigned long long ull;

#define FMA2(d,a,b,c) asm("fma.rn.f32x2 %0, %1, %2, %3;" : "=l"(d) : "l"(a), "l"(b), "l"(c))

__device__ __forceinline__ float hadd2(ull v) {
    float lo, hi; asm("mov.b64 {%0,%1}, %2;" : "=f"(lo), "=f"(hi) : "l"(v)); return lo + hi;
}
__device__ __forceinline__ ull pack2(float a, float b) {
    ull r; asm("mov.b64 %0, {%1,%2};" : "=l"(r) : "f"(a), "f"(b)); return r;
}
__device__ __forceinline__ void unpk2(ull v, float& lo, float& hi) {
    asm("mov.b64 {%0,%1}, %2;" : "=f"(lo), "=f"(hi) : "l"(v));
}

// ---------------- scratch (device globals; allocation-free) ----------------
__device__ __align__(16) float g_seqs[B*L*D];
__device__ __align__(16) float g_tmp [B*L*D];
__device__ __align__(16) float g_Qn  [B*L*D];
__device__ __align__(16) float g_gate[B*E];
__device__ __align__(16) float g_q   [B*E*H*L*DH];   // [be, h, l, dh]
__device__ __align__(16) float g_k   [B*E*H*L*DH];
__device__ __align__(16) float g_v   [B*E*H*L*DH];
__device__ __align__(16) float g_ctx [B*E*L*D];      // [be, l, d]  (gate pre-folded)

// ---------------- gate MLP ----------------
__global__ void k_gate(const float* __restrict__ item_emb,
                       const float* __restrict__ rW1, const float* __restrict__ rb1,
                       const float* __restrict__ rW2, const float* __restrict__ rb2,
                       const int* __restrict__ log_seqs) {
    __shared__ float mean[D];
    __shared__ float h[100];
    __shared__ float logit[E];
    int b = blockIdx.x, t = threadIdx.x;
    if (t < D) {
        float acc = 0.f;
        for (int l = 0; l < L; ++l) {
            int it = log_seqs[b*L + l];
            acc += item_emb[it*D + t];
        }
        mean[t] = acc * (7.0710678118654755f / 200.0f);
    }
    __syncthreads();
    if (t < 100) {
        float acc = rb1[t];
        #pragma unroll
        for (int d = 0; d < D; ++d) acc = fmaf(mean[d], rW1[t*D + d], acc);
        h[t] = fmaxf(acc, 0.f);
    }
    __syncthreads();
    if (t < E) {
        float acc = rb2[t];
        #pragma unroll
        for (int j = 0; j < 100; ++j) acc = fmaf(h[j], rW2[t*100 + j], acc);
        logit[t] = acc;
    }
    __syncthreads();
    if (t == 0) {
        float m = -1e30f;
        #pragma unroll
        for (int e = 0; e < E; ++e) m = fmaxf(m, logit[e]);
        float s = 0.f; float ex[E];
        #pragma unroll
        for (int e = 0; e < E; ++e) { ex[e] = expf(logit[e] - m); s += ex[e]; }
        float inv = 1.0f / s;
        #pragma unroll
        for (int e = 0; e < E; ++e) g_gate[b*E + e] = ex[e] * inv;
    }
}

// ---------------- embedding + positional ----------------
__global__ void k_embed(const float* __restrict__ item_emb,
                        const float* __restrict__ pos_emb,
                        const int* __restrict__ log_seqs) {
    int idx = blockIdx.x*blockDim.x + threadIdx.x;
    if (idx >= B*L*D) return;
    int d = idx % D; int bl = idx / D; int l = bl % L; int b = bl / L;
    int it = log_seqs[b*L + l];
    int pos = (it != 0) ? (l + 1) : 0;
    g_seqs[idx] = item_emb[it*D + d] * 7.0710678118654755f + pos_emb[pos*D + d];
}

// ---------------- layernorm: warp per row ----------------
__global__ void k_ln(int mode, const float* __restrict__ g, const float* __restrict__ bb) {
    int warp = (blockIdx.x*blockDim.x + threadIdx.x) >> 5;
    int lane = threadIdx.x & 31;
    if (warp >= B*L) return;
    const float* in  = (mode == 0) ? g_seqs : g_tmp;
    float*       out = (mode == 0) ? g_Qn   : g_seqs;
    const float* x = in + warp*D;
    float x0 = (lane < D)      ? x[lane]      : 0.f;
    float x1 = (lane + 32 < D) ? x[lane + 32] : 0.f;
    float s = x0 + x1;
    #pragma unroll
    for (int o = 16; o; o >>= 1) s += __shfl_xor_sync(~0u, s, o);
    float m = s * (1.0f / D);
    float d0 = (lane < D)      ? x0 - m : 0.f;
    float d1 = (lane + 32 < D) ? x1 - m : 0.f;
    float v = d0*d0 + d1*d1;
    #pragma unroll
    for (int o = 16; o; o >>= 1) v += __shfl_xor_sync(~0u, v, o);
    float inv = rsqrtf(v * (1.0f / D) + 1e-8f);
    float* y = out + warp*D;
    if (lane < D)      y[lane]      = fmaf(d0*inv, g[lane],      bb[lane]);
    if (lane + 32 < D) y[lane + 32] = fmaf(d1*inv, g[lane + 32], bb[lane + 32]);
}

// ---------------- QKV: CTA per b; register tile 4 rows x 10 feats; dyn smem ----------------
// smem (ull units): XQ @0 [25*201], XS @5025 [25*201], W @10050 [3750], SOUT @13800 [5000],
//                   bias floats @ull 18800
#define QKV_XQ   0
#define QKV_XS   5025
#define QKV_W    10050
#define QKV_SOUT 13800
#define QKV_SMEM_BYTES (18800*8 + 256*4)

__global__ void __launch_bounds__(256) k_qkv(const float* __restrict__ in_w,
                                             const float* __restrict__ in_b, int blk) {
    extern __shared__ __align__(16) ull sm[];
    ull* XQ = sm + QKV_XQ;
    ull* XS = sm + QKV_XS;
    ull* W  = sm + QKV_W;
    ull* SO = sm + QKV_SOUT;
    float* sbias = (float*)(sm + 18800);
    int b = blockIdx.x;
    int tid = threadIdx.x;

    // stage x transposed: XT[i*201 + row] = rowpair(row, k-pair i)
    {
        const ull* gq = (const ull*)g_Qn  + (size_t)b*5000;
        const ull* gs = (const ull*)g_seqs + (size_t)b*5000;
        for (int o = tid; o < 5000; o += 256) {
            int row = o / 25, i = o - row*25;
            XQ[i*201 + row] = gq[o];
            XS[i*201 + row] = gs[o];
        }
    }
    bool act = tid < 250;
    int fg = tid / 50;          // 0..4 (head within pass)
    int rg = tid - fg*50;       // 0..49 -> rows rg, rg+50, rg+100, rg+150

    for (int e = 0; e < E; ++e) {
        __syncthreads();
        {
            const ull* Wg = (const ull*)(in_w + (size_t)(blk*E + e)*7500);
            for (int o = tid; o < 3750; o += 256) {
                int f = o / 25, i = o - f*25;
                W[i*150 + f] = Wg[o];
            }
            for (int o = tid; o < 150; o += 256) sbias[o] = in_b[(blk*E + e)*150 + o];
        }
        __syncthreads();
        for (int pass = 0; pass < 3; ++pass) {
            if (act) {
                const ull* xb = (pass == 0) ? XQ : XS;
                int f0 = pass*50 + fg*10;
                ull acc[4][10];
                #pragma unroll
                for (int r = 0; r < 4; ++r)
                    #pragma unroll
                    for (int j = 0; j < 10; ++j) acc[r][j] = 0ull;
                #pragma unroll 5
                for (int i = 0; i < 25; ++i) {
                    ull xr[4];
                    #pragma unroll
                    for (int r = 0; r < 4; ++r) xr[r] = xb[i*201 + rg + 50*r];
                    const ull* wp = W + i*150 + f0;
                    #pragma unroll
                    for (int j2 = 0; j2 < 5; ++j2) {
                        float4 w4 = *(const float4*)(wp + 2*j2);
                        ull wA = pack2(w4.x, w4.y);
                        ull wB = pack2(w4.z, w4.w);
                        #pragma unroll
                        for (int r = 0; r < 4; ++r) {
                            FMA2(acc[r][2*j2],   wA, xr[r], acc[r][2*j2]);
                            FMA2(acc[r][2*j2+1], wB, xr[r], acc[r][2*j2+1]);
                        }
                    }
                }
                int fb = pass*50 + fg*10;
                #pragma unroll
                for (int r = 0; r < 4; ++r) {
                    int row = rg + 50*r;
                    #pragma unroll
                    for (int j2 = 0; j2 < 5; ++j2) {
                        float v0 = hadd2(acc[r][2*j2])   + sbias[fb + 2*j2];
                        float v1 = hadd2(acc[r][2*j2+1]) + sbias[fb + 2*j2 + 1];
                        SO[row*25 + fg*5 + j2] = pack2(v0, v1);
                    }
                }
            }
            __syncthreads();
            {
                float* arr = (pass == 0) ? g_q : (pass == 1) ? g_k : g_v;
                ull* dst = (ull*)arr + (size_t)(b*E + e)*5000;
                for (int o = tid; o < 5000; o += 256) {
                    int h = o / 1000; int rem = o - h*1000;
                    int l = rem / 5;  int d2 = rem - l*5;
                    dst[o] = SO[l*25 + h*5 + d2];
                }
            }
            __syncthreads();
        }
    }
}

// ---------------- attention: 2 query rows per lane, gate folded in ----------------
__global__ void __launch_bounds__(128) k_attn() {
    int id = blockIdx.x;            // (b*E+e)*H + h
    int h = id % H; int be = id / H;
    __shared__ __align__(16) float ks[L*DH];
    __shared__ __align__(16) float vs[L*DH];
    {
        const float4* kb = (const float4*)(g_k + (size_t)(be*H + h)*L*DH);
        const float4* vb = (const float4*)(g_v + (size_t)(be*H + h)*L*DH);
        float4* k4 = (float4*)ks; float4* v4 = (float4*)vs;
        for (int i = threadIdx.x; i < 500; i += 128) { k4[i] = kb[i]; v4[i] = vb[i]; }
    }
    __syncthreads();
    int w = threadIdx.x >> 5, lane = threadIdx.x & 31;
    int r0 = w*64 + lane*2, r1 = r0 + 1;
    bool v0 = r0 < L, v1 = r1 < L;
    int i0 = v0 ? r0 : 0, i1 = v1 ? r1 : 0;
    const float scale = 0.31622776601683794f;   // 1/sqrt(10)
    ull q0[5], q1[5];
    {
        const ull* qb = (const ull*)g_q + (size_t)(be*H + h)*1000;
        const ull* p0 = qb + i0*5; const ull* p1 = qb + i1*5;
        #pragma unroll
        for (int d = 0; d < 5; ++d) { q0[d] = p0[d]; q1[d] = p1[d]; }
    }
    int jmax = w*64 + 64; if (jmax > L) jmax = L;
    float ps0 = 0.f, ps1 = 0.f;
    ull a0[5] = {0,0,0,0,0}, a1[5] = {0,0,0,0,0};
    #pragma unroll 2
    for (int j = 0; j < jmax; ++j) {
        const ull* kj = (const ull*)ks + j*5;
        const ull* vj = (const ull*)vs + j*5;
        ull s0 = 0ull, s1 = 0ull;
        #pragma unroll
        for (int d = 0; d < 5; ++d) {
            ull kd = kj[d];
            FMA2(s0, q0[d], kd, s0);
            FMA2(s1, q1[d], kd, s1);
        }
        float sc0 = hadd2(s0) * scale;
        float sc1 = hadd2(s1) * scale;
        float p0 = (j <= r0) ? __expf(sc0) : 0.f;
        float p1 = (j <= r1) ? __expf(sc1) : 0.f;
        ps0 += p0; ps1 += p1;
        ull pp0 = pack2(p0, p0), pp1 = pack2(p1, p1);
        #pragma unroll
        for (int d = 0; d < 5; ++d) {
            ull vd = vj[d];
            FMA2(a0[d], pp0, vd, a0[d]);
            FMA2(a1[d], pp1, vd, a1[d]);
        }
    }
    int b = be / E, e = be - b*E;
    float gt = g_gate[b*E + e];
    if (v0) {
        float inv = gt / ps0;
        ull* cp = (ull*)g_ctx + ((size_t)be*L + r0)*25 + h*5;
        #pragma unroll
        for (int d = 0; d < 5; ++d) { float lo, hi; unpk2(a0[d], lo, hi); cp[d] = pack2(lo*inv, hi*inv); }
    }
    if (v1) {
        float inv = gt / ps1;
        ull* cp = (ull*)g_ctx + ((size_t)be*L + r1)*25 + h*5;
        #pragma unroll
        for (int d = 0; d < 5; ++d) { float lo, hi; unpk2(a1[d], lo, hi); cp[d] = pack2(lo*inv, hi*inv); }
    }
}

// ---------------- out-proj + bias-mix + residual: CTA per (b, half); 2x10 reg tile ----------------
__global__ void __launch_bounds__(256) k_combine(const float* __restrict__ out_w,
                                                 const float* __restrict__ out_b, int blk) {
    __shared__ __align__(16) ull CT[2525];   // transposed ctx [i*101 + row], 100 rows; reused as SOUT
    __shared__ __align__(16) ull WT[1250];   // [i*50 + f-pairs... i*50+f] W[f][2i..2i+1]
    int b = blockIdx.x;
    int l0 = blockIdx.y * 100;
    int tid = threadIdx.x;
    bool act = tid < 250;
    int fg = tid / 50;           // 0..4
    int rg = tid - fg*50;        // rows rg, rg+50 (local)
    ull acc[2][10];
    #pragma unroll
    for (int r = 0; r < 2; ++r)
        #pragma unroll
        for (int j = 0; j < 10; ++j) acc[r][j] = 0ull;
    float bm[10];
    #pragma unroll
    for (int j = 0; j < 10; ++j) bm[j] = 0.f;

    for (int e = 0; e < E; ++e) {
        __syncthreads();
        {
            const ull* Wg = (const ull*)(out_w + (size_t)(blk*E + e)*2500);
            for (int o = tid; o < 1250; o += 256) {
                int f = o / 25, i = o - f*25;
                WT[i*50 + f] = Wg[o];
            }
            const ull* cg = (const ull*)g_ctx + ((size_t)(b*E + e)*L + l0)*25;
            for (int o = tid; o < 2500; o += 256) {
                int row = o / 25, i = o - row*25;
                CT[i*101 + row] = cg[o];
            }
        }
        float ge = g_gate[b*E + e];
        if (act) {
            #pragma unroll
            for (int j = 0; j < 10; ++j)
                bm[j] = fmaf(ge, out_b[(blk*E + e)*D + fg*10 + j], bm[j]);
        }
        __syncthreads();
        if (act) {
            #pragma unroll 5
            for (int i = 0; i < 25; ++i) {
                ull x0 = CT[i*101 + rg];
                ull x1 = CT[i*101 + rg + 50];
                const ull* wp = WT + i*50 + fg*10;
                #pragma unroll
                for (int j2 = 0; j2 < 5; ++j2) {
                    float4 w4 = *(const float4*)(wp + 2*j2);
                    ull wA = pack2(w4.x, w4.y);
                    ull wB = pack2(w4.z, w4.w);
                    FMA2(acc[0][2*j2],   wA, x0, acc[0][2*j2]);
                    FMA2(acc[0][2*j2+1], wB, x0, acc[0][2*j2+1]);
                    FMA2(acc[1][2*j2],   wA, x1, acc[1][2*j2]);
                    FMA2(acc[1][2*j2+1], wB, x1, acc[1][2*j2+1]);
                }
            }
        }
    }
    __syncthreads();
    if (act) {
        #pragma unroll
        for (int r = 0; r < 2; ++r) {
            int row = rg + 50*r;
            #pragma unroll
            for (int j2 = 0; j2 < 5; ++j2) {
                float v0 = hadd2(acc[r][2*j2])   + bm[2*j2];
                float v1 = hadd2(acc[r][2*j2+1]) + bm[2*j2+1];
                CT[row*25 + fg*5 + j2] = pack2(v0, v1);
            }
        }
    }
    __syncthreads();
    {
        const ull* qn = (const ull*)g_Qn + ((size_t)b*L + l0)*25;
        ull* dst = (ull*)g_tmp + ((size_t)b*L + l0)*25;
        for (int o = tid; o < 2500; o += 256) {
            float a, bb2, c, d;
            unpk2(CT[o], a, bb2);
            unpk2(qn[o], c, d);
            dst[o] = pack2(a + c, bb2 + d);
        }
    }
}

// ---------------- fused FFN (in place on g_seqs) ----------------
__global__ void __launch_bounds__(250) k_ffn(const float* __restrict__ f1_w, const float* __restrict__ f1_b,
                                             const float* __restrict__ f2_w, const float* __restrict__ f2_b,
                                             int blk) {
    int b = blockIdx.x;
    int base = blockIdx.y * 100;
    __shared__ __align__(16) float w1t[2500], w2t[2500];
    __shared__ __align__(16) float xs[500];
    __shared__ __align__(16) float hs[520];
    __shared__ float b1s[50], b2s[50];
    int tid = threadIdx.x;
    int fc2 = tid % 25, r = tid / 25;
    {
        const ull* W1g = (const ull*)(f1_w + (size_t)blk*2500);
        const ull* W2g = (const ull*)(f2_w + (size_t)blk*2500);
        ull* w1u = (ull*)w1t; ull* w2u = (ull*)w2t;
        for (int j = tid; j < 1250; j += 250) {
            int f = j / 25, i = j - f*25;
            w1u[i*50 + f] = W1g[j];
            w2u[i*50 + f] = W2g[j];
        }
        if (tid < 50) { b1s[tid] = f1_b[blk*D + tid]; b2s[tid] = f2_b[blk*D + tid]; }
    }
    __syncthreads();
    for (int chunk = 0; chunk < 10; ++chunk) {
        int l0 = base + chunk*10;
        for (int j = tid; j < 500; j += 250) xs[j] = g_seqs[((size_t)b*L + l0)*D + j];
        __syncthreads();
        const ull* xp = (const ull*)(xs + r*50);
        ull a0 = 0ull, a1 = 0ull;
        #pragma unroll
        for (int i = 0; i < 25; ++i) {
            float4 w4 = *(const float4*)(w1t + i*100 + 4*fc2);
            FMA2(a0, pack2(w4.x, w4.y), xp[i], a0);
            FMA2(a1, pack2(w4.z, w4.w), xp[i], a1);
        }
        float h0 = fmaxf(hadd2(a0) + b1s[2*fc2],     0.f);
        float h1 = fmaxf(hadd2(a1) + b1s[2*fc2 + 1], 0.f);
        *(ull*)(hs + r*52 + 2*fc2) = pack2(h0, h1);
        __syncthreads();
        const ull* hp = (const ull*)(hs + r*52);
        a0 = 0ull; a1 = 0ull;
        #pragma unroll
        for (int i = 0; i < 25; ++i) {
            float4 w4 = *(const float4*)(w2t + i*100 + 4*fc2);
            FMA2(a0, pack2(w4.x, w4.y), hp[i], a0);
            FMA2(a1, pack2(w4.z, w4.w), hp[i], a1);
        }
        float o0 = hadd2(a0) + b2s[2*fc2]     + xs[r*50 + 2*fc2];
        float o1 = hadd2(a1) + b2s[2*fc2 + 1] + xs[r*50 + 2*fc2 + 1];
        *(ull*)(g_seqs + ((size_t)b*L + l0 + r)*D + 2*fc2) = pack2(o0, o1);
        __syncthreads();
    }
}

// ---------------- final LN + pos/neg logits ----------------
__global__ void k_final(const float* __restrict__ lnf_g, const float* __restrict__ lnf_b,
                        const float* __restrict__ item_emb,
                        const int* __restrict__ pos_seqs, const int* __restrict__ neg_seqs,
                        float* __restrict__ out) {
    int warp = (blockIdx.x*blockDim.x + threadIdx.x) >> 5;
    int lane = threadIdx.x & 31;
    if (warp >= B*L) return;
    const float* x = g_seqs + warp*D;
    float x0 = (lane < D)      ? x[lane]      : 0.f;
    float x1 = (lane + 32 < D) ? x[lane + 32] : 0.f;
    float s = x0 + x1;
    #pragma unroll
    for (int o = 16; o; o >>= 1) s += __shfl_xor_sync(~0u, s, o);
    float m = s * (1.0f / D);
    float d0 = (lane < D)      ? x0 - m : 0.f;
    float d1 = (lane + 32 < D) ? x1 - m : 0.f;
    float v = d0*d0 + d1*d1;
    #pragma unroll
    for (int o = 16; o; o >>= 1) v += __shfl_xor_sync(~0u, v, o);
    float inv = rsqrtf(v * (1.0f / D) + 1e-8f);
    float f0 = (lane < D)      ? fmaf(d0*inv, lnf_g[lane],      lnf_b[lane])      : 0.f;
    float f1 = (lane + 32 < D) ? fmaf(d1*inv, lnf_g[lane + 32], lnf_b[lane + 32]) : 0.f;
    int ip = pos_seqs[warp], in_ = neg_seqs[warp];
    const float* pe = item_emb + (size_t)ip*D;
    const float* ne = item_emb + (size_t)in_*D;
    float dp = 0.f, dn = 0.f;
    if (lane < D)      { dp = f0*pe[lane];                 dn = f0*ne[lane]; }
    if (lane + 32 < D) { dp = fmaf(f1, pe[lane + 32], dp); dn = fmaf(f1, ne[lane + 32], dn); }
    #pragma unroll
    for (int o = 16; o; o >>= 1) {
        dp += __shfl_xor_sync(~0u, dp, o);
        dn += __shfl_xor_sync(~0u, dn, o);
    }
    if (lane == 0) { out[warp] = dp; out[B*L + warp] = dn; }
}

// ---------------- launch ----------------
extern "C" void kernel_launch(void* const* d_in, const int* in_sizes, int n_in,
                              void* d_out, int out_size) {
    const float* item_emb = (const float*)d_in[0];
    const float* pos_emb  = (const float*)d_in[1];
    const float* rW1      = (const float*)d_in[2];
    const float* rb1      = (const float*)d_in[3];
    const float* rW2      = (const float*)d_in[4];
    const float* rb2      = (const float*)d_in[5];
    const float* ln1_g    = (const float*)d_in[6];
    const float* ln1_b    = (const float*)d_in[7];
    const float* in_w     = (const float*)d_in[8];
    const float* in_b     = (const float*)d_in[9];
    const float* out_w    = (const float*)d_in[10];
    const float* out_b    = (const float*)d_in[11];
    const float* ln2_g    = (const float*)d_in[12];
    const float* ln2_b    = (const float*)d_in[13];
    const float* f1_w     = (const float*)d_in[14];
    const float* f1_b     = (const float*)d_in[15];
    const float* f2_w     = (const float*)d_in[16];
    const float* f2_b     = (const float*)d_in[17];
    const float* lnf_g    = (const float*)d_in[18];
    const float* lnf_b    = (const float*)d_in[19];
    const int*   log_seqs = (const int*)d_in[21];
    const int*   pos_seqs = (const int*)d_in[22];
    const int*   neg_seqs = (const int*)d_in[23];
    float* out = (float*)d_out;

    cudaFuncSetAttribute(k_qkv, cudaFuncAttributeMaxDynamicSharedMemorySize, QKV_SMEM_BYTES);

    k_gate<<<B, 128>>>(item_emb, rW1, rb1, rW2, rb2, log_seqs);
    k_embed<<<(B*L*D + 255)/256, 256>>>(item_emb, pos_emb, log_seqs);

    for (int blk = 0; blk < NB; ++blk) {
        k_ln<<<(B*L + 7)/8, 256>>>(0, ln1_g + blk*D, ln1_b + blk*D);
        k_qkv<<<B, 256, QKV_SMEM_BYTES>>>(in_w, in_b, blk);
        k_attn<<<B*E*H, 128>>>();
        k_combine<<<dim3(B, 2), 256>>>(out_w, out_b, blk);
        k_ln<<<(B*L + 7)/8, 256>>>(1, ln2_g + blk*D, ln2_b + blk*D);
        k_ffn<<<dim3(B, 2), 250>>>(f1_w, f1_b, f2_w, f2_b, blk);
    }

    k_final<<<(B*L + 7)/8, 256>>>(lnf_g, lnf_b, item_emb, pos_seqs, neg_seqs, out);
}